// round 13
// baseline (speedup 1.0000x reference)
#include <cuda_runtime.h>

#define NT 5
#define A_FIX 128
#define MAXP 65          // max atom-pairs of one type (ceil(128/2)+1 pad)
#define THREADS 256
#define PTS_PER_BLK (THREADS * 2)   // 512: 2 points per thread

typedef unsigned long long ull;

__device__ __forceinline__ float fast_sqrt(float x) {
    float r; asm("sqrt.approx.f32 %0, %1;" : "=f"(r) : "f"(x)); return r;
}
__device__ __forceinline__ float fast_ex2(float x) {
    float r; asm("ex2.approx.f32 %0, %1;" : "=f"(r) : "f"(x)); return r;
}
__device__ __forceinline__ float fast_rcp(float x) {
    float r; asm("rcp.approx.f32 %0, %1;" : "=f"(r) : "f"(x)); return r;
}
__device__ __forceinline__ float fast_rsq(float x) {
    float r; asm("rsqrt.approx.f32 %0, %1;" : "=f"(r) : "f"(x)); return r;
}

__device__ __forceinline__ ull pack2(float lo, float hi) {
    ull r;
    asm("mov.b64 %0, {%1, %2};" : "=l"(r) : "r"(__float_as_uint(lo)), "r"(__float_as_uint(hi)));
    return r;
}
__device__ __forceinline__ void unpack2(ull v, float& lo, float& hi) {
    unsigned int a, b;
    asm("mov.b64 {%0, %1}, %2;" : "=r"(a), "=r"(b) : "l"(v));
    lo = __uint_as_float(a); hi = __uint_as_float(b);
}
__device__ __forceinline__ ull ffma2(ull a, ull b, ull c) {
    ull d; asm("fma.rn.f32x2 %0, %1, %2, %3;" : "=l"(d) : "l"(a), "l"(b), "l"(c)); return d;
}
__device__ __forceinline__ ull fadd2(ull a, ull b) {
    ull d; asm("add.rn.f32x2 %0, %1, %2;" : "=l"(d) : "l"(a), "l"(b)); return d;
}

// one atom-PAIR (from shared loads xy, zw) against point k's constants,
// accumulating into point k's bank
#define PAIRP(xy, zw, NQX, NQY, NQZ, NQQ, SW, SX, SY, SZ)                      \
    {                                                                          \
        ull dot = ffma2((xy).x, NQX, ffma2((xy).y, NQY,                        \
                     ffma2((zw).x, NQZ, NQQ)));     /* -2c.q + |q|^2 */        \
        ull d2p = fadd2((zw).y, dot);               /* |c-q|^2 both atoms */   \
        float d0, d1; unpack2(d2p, d0, d1);                                    \
        float e0 = fast_ex2(-fast_sqrt(fabsf(d0)));                            \
        float e1 = fast_ex2(-fast_sqrt(fabsf(d1)));                            \
        ull e2 = pack2(e0, e1);                                                \
        SW = fadd2(SW, e2);                                                    \
        SX = ffma2(e2, (xy).x, SX);                                            \
        SY = ffma2(e2, (xy).y, SY);                                            \
        SZ = ffma2(e2, (zw).x, SZ);                                            \
    }

__global__ __launch_bounds__(THREADS, 4) void gnf_kernel(
    const float* __restrict__ coords,    // [B, A, 3]
    const int*   __restrict__ atom_types,// [B, A]
    const float* __restrict__ query,     // [B, P, 3]
    float*       __restrict__ out,       // [B, P, NT, 3]
    int P)
{
    // interleaved atom-pair SoA: sAT[2j] = (xa,xb,ya,yb), sAT[2j+1] = (za,zb,wa,wb)
    __shared__ __align__(16) float sAT[MAXP * 8];
    __shared__ int cnt;

    const int b   = blockIdx.y;
    const int ty  = blockIdx.z;
    const int tid = threadIdx.x;
    const float L = 1.4426950408889634f;   // log2(e)

    if (tid == 0) cnt = 0;
    // sentinel fill: w = 1e30 -> e == 0 exactly
    for (int i = tid; i < MAXP * 8; i += THREADS)
        sAT[i] = ((i & 7) >= 6) ? 1e30f : 0.0f;
    __syncthreads();

    // ballot-based bucketing: 1 atomic per warp, popc ranks
    {
        const bool mine = (tid < A_FIX) && (atom_types[b * A_FIX + tid] == ty);
        const unsigned mask = __ballot_sync(0xFFFFFFFFu, mine);
        const int lane = tid & 31;
        int base = 0;
        if (mask) {
            if (lane == 0) base = atomicAdd(&cnt, __popc(mask));
            base = __shfl_sync(0xFFFFFFFFu, base, 0);
        }
        if (mine) {
            int r = base + __popc(mask & ((1u << lane) - 1u));
            const float* c = coords + (b * A_FIX + tid) * 3;
            float x = c[0] * L, y = c[1] * L, z = c[2] * L;
            float w = fmaf(x, x, fmaf(y, y, z * z));
            int j = r >> 1, h = r & 1;
            sAT[8 * j + h]     = x;
            sAT[8 * j + 2 + h] = y;
            sAT[8 * j + 4 + h] = z;
            sAT[8 * j + 6 + h] = w;
        }
    }
    __syncthreads();

    const int n   = cnt;
    const int npj = (n + 1) >> 1;          // atom-pairs (sentinel-padded)

    const int p0 = blockIdx.x * PTS_PER_BLK + tid;        // first point
    const int p1 = p0 + THREADS;                          // second point
    if (p0 >= P) return;

    // packed per-point constants (atom-pair lanes are duplicated)
    ull nqx0, nqy0, nqz0, nqq0, nqx1, nqy1, nqz1, nqq1;
    {
        const float* q = query + ((long)b * P + p0) * 3;
        float qx = q[0] * L, qy = q[1] * L, qz = q[2] * L;
        float qq = fmaf(qx, qx, fmaf(qy, qy, qz * qz));
        nqx0 = pack2(-2.0f * qx, -2.0f * qx);
        nqy0 = pack2(-2.0f * qy, -2.0f * qy);
        nqz0 = pack2(-2.0f * qz, -2.0f * qz);
        nqq0 = pack2(qq, qq);
    }
    {
        const int cp1 = (p1 < P) ? p1 : p0;
        const float* q = query + ((long)b * P + cp1) * 3;
        float qx = q[0] * L, qy = q[1] * L, qz = q[2] * L;
        float qq = fmaf(qx, qx, fmaf(qy, qy, qz * qz));
        nqx1 = pack2(-2.0f * qx, -2.0f * qx);
        nqy1 = pack2(-2.0f * qy, -2.0f * qy);
        nqz1 = pack2(-2.0f * qz, -2.0f * qz);
        nqq1 = pack2(qq, qq);
    }

    const ulonglong2* pA = (const ulonglong2*)sAT;

    // one bank per point; each PAIRP has 2 independent MUFU chains
    ull w0 = 0, x0 = 0, y0 = 0, z0 = 0;
    ull w1 = 0, x1 = 0, y1 = 0, z1 = 0;

    for (int j = 0; j < npj; j++) {
        ulonglong2 xy = pA[2 * j], zw = pA[2 * j + 1];    // shared by both points
        PAIRP(xy, zw, nqx0, nqy0, nqz0, nqq0, w0, x0, y0, z0);
        PAIRP(xy, zw, nqx1, nqy1, nqz1, nqq1, w1, x1, y1, z1);
    }

    const float INVL = 0.6931471805599453f;  // ln(2)

    // ---- epilogue point 0 ----
    {
        float swl, swh, sxl, sxh, syl, syh, szl, szh, qx2, qy2, qz2, dummy;
        unpack2(w0, swl, swh); unpack2(x0, sxl, sxh);
        unpack2(y0, syl, syh); unpack2(z0, szl, szh);
        unpack2(nqx0, qx2, dummy); unpack2(nqy0, qy2, dummy); unpack2(nqz0, qz2, dummy);
        float qx = -0.5f * qx2, qy = -0.5f * qy2, qz = -0.5f * qz2;
        float sw = swl + swh, sxc = sxl + sxh, syc = syl + syh, szc = szl + szh;
        float gx = 0.f, gy = 0.f, gz = 0.f;
        if (n > 0) {
            float inv = fast_rcp(sw) * INVL;
            gx = (sxc - qx * sw) * inv;
            gy = (syc - qy * sw) * inv;
            gz = (szc - qz * sw) * inv;
            float g2 = fmaf(gx, gx, fmaf(gy, gy, gz * gz));
            float f = fminf(1.0f, 0.3f * fast_rsq(fmaxf(g2, 1e-24f)));
            gx *= f; gy *= f; gz *= f;
        }
        float* o = out + (((long)b * P + p0) * NT + ty) * 3;
        o[0] = gx; o[1] = gy; o[2] = gz;
    }
    // ---- epilogue point 1 ----
    if (p1 < P) {
        float swl, swh, sxl, sxh, syl, syh, szl, szh, qx2, qy2, qz2, dummy;
        unpack2(w1, swl, swh); unpack2(x1, sxl, sxh);
        unpack2(y1, syl, syh); unpack2(z1, szl, szh);
        unpack2(nqx1, qx2, dummy); unpack2(nqy1, qy2, dummy); unpack2(nqz1, qz2, dummy);
        float qx = -0.5f * qx2, qy = -0.5f * qy2, qz = -0.5f * qz2;
        float sw = swl + swh, sxc = sxl + sxh, syc = syl + syh, szc = szl + szh;
        float gx = 0.f, gy = 0.f, gz = 0.f;
        if (n > 0) {
            float inv = fast_rcp(sw) * INVL;
            gx = (sxc - qx * sw) * inv;
            gy = (syc - qy * sw) * inv;
            gz = (szc - qz * sw) * inv;
            float g2 = fmaf(gx, gx, fmaf(gy, gy, gz * gz));
            float f = fminf(1.0f, 0.3f * fast_rsq(fmaxf(g2, 1e-24f)));
            gx *= f; gy *= f; gz *= f;
        }
        float* o = out + (((long)b * P + p1) * NT + ty) * 3;
        o[0] = gx; o[1] = gy; o[2] = gz;
    }
}

extern "C" void kernel_launch(void* const* d_in, const int* in_sizes, int n_in,
                              void* d_out, int out_size)
{
    const float* coords     = (const float*)d_in[0];  // B*A*3
    const int*   atom_types = (const int*)  d_in[1];  // B*A
    const float* query      = (const float*)d_in[2];  // B*P*3

    const int A = A_FIX;
    const int B = in_sizes[1] / A;
    const int P = in_sizes[2] / (3 * B);

    dim3 grid((P + PTS_PER_BLK - 1) / PTS_PER_BLK, B, NT);
    gnf_kernel<<<grid, THREADS>>>(coords, atom_types, query, (float*)d_out, P);
}